// round 15
// baseline (speedup 1.0000x reference)
#include <cuda_runtime.h>
#include <cuda_bf16.h>
#include <cstdint>

// ---------------- model constants ----------------
#define NL     2
#define D      768
#define DI     1536
#define NSTATE 16
#define DR     48
#define KCONV  4
#define VOC    32000
#define BB     2
#define LSEQ   1024
#define TOK    (BB*LSEQ)        // 2048
#define BCDW   (2*NSTATE+DR)    // 80
#define EPS    1e-5f
#define BCD_SPLIT 8
#define BCD_KCHUNK (DI/BCD_SPLIT)   // 192

// ---------------- scratch ----------------
__device__ __align__(256) float g_h [TOK*D];
__device__ __align__(256) float g_xz[TOK*2*DI];
__device__ __align__(256) float g_xi[TOK*DI];
__device__ __align__(256) float g_bcd[TOK*BCDW];
__device__ __align__(256) float g_bcdp[BCD_SPLIT*TOK*BCDW];
__device__ __align__(256) float g_delta[TOK*DI];
__device__ __align__(256) __nv_bfloat16 g_eh[VOC*D];
__device__ __align__(256) __nv_bfloat16 g_el[VOC*D];
__device__ __align__(256) __nv_bfloat16 g_wh[2*DI*D];
__device__ __align__(256) __nv_bfloat16 g_wl[2*DI*D];
__device__ __align__(256) __nv_bfloat16 g_ah[TOK*DI];
__device__ __align__(256) __nv_bfloat16 g_al[TOK*DI];

// ---------------- helpers ----------------
__device__ __forceinline__ uint32_t s2u(const void* p) {
    uint32_t a;
    asm("{ .reg .u64 t; cvta.to.shared.u64 t, %1; cvt.u32.u64 %0, t; }" : "=r"(a) : "l"(p));
    return a;
}
__device__ __forceinline__ void cp16(uint32_t saddr, const void* gaddr, int sz) {
    asm volatile("cp.async.cg.shared.global [%0], [%1], 16, %2;"
                 :: "r"(saddr), "l"(gaddr), "r"(sz) : "memory");
}
__device__ __forceinline__ void ldmx4(uint32_t* r, uint32_t addr) {
    asm volatile("ldmatrix.sync.aligned.m8n8.x4.shared.b16 {%0,%1,%2,%3}, [%4];"
                 : "=r"(r[0]), "=r"(r[1]), "=r"(r[2]), "=r"(r[3]) : "r"(addr));
}
__device__ __forceinline__ void mma16816(float* c, const uint32_t* a, const uint32_t* b) {
    asm volatile("mma.sync.aligned.m16n8k16.row.col.f32.bf16.bf16.f32 "
                 "{%0,%1,%2,%3}, {%4,%5,%6,%7}, {%8,%9}, {%0,%1,%2,%3};"
                 : "+f"(c[0]), "+f"(c[1]), "+f"(c[2]), "+f"(c[3])
                 : "r"(a[0]), "r"(a[1]), "r"(a[2]), "r"(a[3]), "r"(b[0]), "r"(b[1]));
}
__device__ __forceinline__ uint32_t pkbf2(float a, float b) {
    return (uint32_t)__bfloat16_as_ushort(__float2bfloat16(a))
         | ((uint32_t)__bfloat16_as_ushort(__float2bfloat16(b)) << 16);
}

// ---------------- vectorized bf16 hi/lo split (8 elems / thread) ----------
__global__ void cvt8_k(const float* __restrict__ src, __nv_bfloat16* __restrict__ hi,
                       __nv_bfloat16* __restrict__ lo, int rows, int K, int Kpad,
                       int lda, int off) {
    int cpr = Kpad >> 3;
    int idx = blockIdx.x * blockDim.x + threadIdx.x;
    if (idx >= rows * cpr) return;
    int r = idx / cpr, c = idx - r * cpr;
    int k0 = c << 3;
    float v[8];
    if (k0 + 8 <= K) {
        const float4* p = (const float4*)(src + (size_t)r * lda + off + k0);
        float4 x0 = p[0], x1 = p[1];
        v[0]=x0.x; v[1]=x0.y; v[2]=x0.z; v[3]=x0.w;
        v[4]=x1.x; v[5]=x1.y; v[6]=x1.z; v[7]=x1.w;
    } else {
        #pragma unroll
        for (int j = 0; j < 8; j++)
            v[j] = (k0 + j < K) ? src[(size_t)r * lda + off + k0 + j] : 0.f;
    }
    uint4 hp, lp;
    uint32_t* hq = (uint32_t*)&hp; uint32_t* lq = (uint32_t*)&lp;
    #pragma unroll
    for (int j = 0; j < 4; j++) {
        float a = v[2*j], b = v[2*j+1];
        float ha = __bfloat162float(__float2bfloat16(a));
        float hb = __bfloat162float(__float2bfloat16(b));
        hq[j] = pkbf2(a, b);
        lq[j] = pkbf2(a - ha, b - hb);
    }
    ((uint4*)hi)[idx] = hp;
    ((uint4*)lo)[idx] = lp;
}

// ---------------- HMMA split-bf16 NT GEMM ----------------
// CTA 128x256, 256 threads, warp tile 64x64 (2x4 warp grid), BK=32,
// 4-stage cp.async, single __syncthreads per k-iter, A-frags streamed.
// smem row = 32 bf16 = 64B; swizzle: chunk c ^= (r>>1)&3 (ldmatrix conflict-free)
#define GS_STAGES 4
#define GS_BYTES  49152   // per stage: Ah 8K | Al 8K | Bh 16K | Bl 16K
#define SWZ32(r,c) ((uint32_t)((r) * 64 + (((c) ^ (((r) >> 1) & 3)) << 4)))

__global__ void __launch_bounds__(256, 1) gemm_mma(
    const __nv_bfloat16* __restrict__ Ah, const __nv_bfloat16* __restrict__ Al,
    const __nv_bfloat16* __restrict__ Bh, const __nv_bfloat16* __restrict__ Bl,
    float* __restrict__ C, int Nn, int Kpad, int Kloop, int ldc, int accum,
    int partStride) {
    extern __shared__ __align__(1024) char gsm[];
    const uint32_t sb = s2u(gsm);
    const int tid = threadIdx.x, lane = tid & 31, wid = tid >> 5;
    const int bm = blockIdx.x * 128, bn = blockIdx.y * 256;
    const int mw = wid & 1, nw = wid >> 1;     // warp tile: 64(M) x 64(N)
    const int nK = Kloop >> 5;
    const int kOff = blockIdx.z * Kloop;
    C += (size_t)blockIdx.z * partStride;

    auto issue = [&](int s) {
        if (s < nK) {
            uint32_t buf = sb + (s & (GS_STAGES - 1)) * GS_BYTES;
            int kb = kOff + (s << 5);
            // A: 128 rows x 4 chunks; thread -> row tid>>1, chunks {(tid&1)*2, +1}
            {
                int r = tid >> 1;
                size_t ga = (size_t)(bm + r) * Kpad + kb;
                #pragma unroll
                for (int q = 0; q < 2; q++) {
                    int c = (tid & 1) * 2 + q;
                    uint32_t so = SWZ32(r, c);
                    cp16(buf + so,        Ah + ga + (c << 3), 16);
                    cp16(buf + 8192 + so, Al + ga + (c << 3), 16);
                }
            }
            // B: 256 rows x 4 chunks
            #pragma unroll
            for (int p = 0; p < 4; p++) {
                int idx = tid + (p << 8);
                int r = idx >> 2, c = idx & 3;
                int rb = bn + r;
                int sz = (rb < Nn) ? 16 : 0;
                size_t gb = (size_t)((rb < Nn) ? rb : 0) * Kpad + kb;
                uint32_t so = SWZ32(r, c);
                cp16(buf + 16384 + so, Bh + gb + (c << 3), sz);
                cp16(buf + 32768 + so, Bl + gb + (c << 3), sz);
            }
        }
        asm volatile("cp.async.commit_group;" ::: "memory");
    };

    float acc[4][8][4];
    #pragma unroll
    for (int i = 0; i < 4; i++)
        #pragma unroll
        for (int j = 0; j < 8; j++)
            #pragma unroll
            for (int v = 0; v < 4; v++) acc[i][j][v] = 0.f;

    const int lrow8 = (lane & 7) + ((lane >> 3) & 1) * 8;
    const int lkh   = lane >> 4;

    #pragma unroll
    for (int s = 0; s < GS_STAGES - 1; s++) issue(s);

    for (int it = 0; it < nK; ++it) {
        asm volatile("cp.async.wait_group %0;" :: "n"(GS_STAGES - 2) : "memory");
        __syncthreads();
        uint32_t base = sb + (it & (GS_STAGES - 1)) * GS_BYTES;
        #pragma unroll
        for (int kc = 0; kc < 2; kc++) {
            int cc = kc * 2 + lkh;
            uint32_t bh[8][2], bl[8][2];
            #pragma unroll
            for (int nb = 0; nb < 4; nb++) {
                int r = nw * 64 + nb * 16 + lrow8;
                uint32_t bd = base + 16384 + SWZ32(r, cc);
                uint32_t t[4];
                ldmx4(t, bd);
                bh[nb*2][0]=t[0]; bh[nb*2+1][0]=t[1]; bh[nb*2][1]=t[2]; bh[nb*2+1][1]=t[3];
                ldmx4(t, bd + 16384);
                bl[nb*2][0]=t[0]; bl[nb*2+1][0]=t[1]; bl[nb*2][1]=t[2]; bl[nb*2+1][1]=t[3];
            }
            #pragma unroll
            for (int ma = 0; ma < 4; ma++) {
                int r = mw * 64 + ma * 16 + lrow8;
                uint32_t ad = base + SWZ32(r, cc);
                uint32_t ah4[4], al4[4];
                ldmx4(ah4, ad);
                ldmx4(al4, ad + 8192);
                #pragma unroll
                for (int na = 0; na < 8; na++) mma16816(acc[ma][na], ah4, bh[na]);
                #pragma unroll
                for (int na = 0; na < 8; na++) mma16816(acc[ma][na], ah4, bl[na]);
                #pragma unroll
                for (int na = 0; na < 8; na++) mma16816(acc[ma][na], al4, bh[na]);
            }
        }
        issue(it + GS_STAGES - 1);
    }

    // epilogue
    #pragma unroll
    for (int ma = 0; ma < 4; ma++) {
        int row0 = bm + mw * 64 + ma * 16 + (lane >> 2);
        #pragma unroll
        for (int na = 0; na < 8; na++) {
            int col = bn + nw * 64 + na * 8 + (lane & 3) * 2;
            if (col < Nn) {
                float* p0 = C + (size_t)row0 * ldc + col;
                float* p1 = C + (size_t)(row0 + 8) * ldc + col;
                float2 v0 = make_float2(acc[ma][na][0], acc[ma][na][1]);
                float2 v1 = make_float2(acc[ma][na][2], acc[ma][na][3]);
                if (accum) {
                    float2 o0 = *(float2*)p0, o1 = *(float2*)p1;
                    v0.x += o0.x; v0.y += o0.y; v1.x += o1.x; v1.y += o1.y;
                }
                *(float2*)p0 = v0;
                *(float2*)p1 = v1;
            }
        }
    }
}

// ---------------- split-K reduce (fixed order -> deterministic) ------------
__global__ void redk(const float* __restrict__ part, float* __restrict__ outp) {
    int i = blockIdx.x * blockDim.x + threadIdx.x;
    if (i >= TOK * BCDW) return;
    float s = 0.f;
    #pragma unroll
    for (int z = 0; z < BCD_SPLIT; z++) s += part[(size_t)z * TOK * BCDW + i];
    outp[i] = s;
}

// ---------------- embedding gather ----------------
__global__ void embed_k(const int* __restrict__ x, const float* __restrict__ emb,
                        float* __restrict__ h) {
    int t = blockIdx.x;
    int v = x[t];
    const float4* src = (const float4*)(emb + (size_t)v * D);
    float4* dst = (float4*)(h + (size_t)t * D);
    for (int i = threadIdx.x; i < D / 4; i += blockDim.x) dst[i] = src[i];
}

// ---------------- rmsnorm -> bf16 hi/lo ----------------
__global__ void rmsnorm_bf_k(const float* __restrict__ in, const float* __restrict__ w,
                             __nv_bfloat16* __restrict__ hi, __nv_bfloat16* __restrict__ lo) {
    int t = blockIdx.x;
    const float* row = in + (size_t)t * D;
    float s = 0.f;
    for (int i = threadIdx.x; i < D; i += blockDim.x) { float v = row[i]; s += v * v; }
    __shared__ float red[8];
    #pragma unroll
    for (int o = 16; o; o >>= 1) s += __shfl_xor_sync(0xffffffffu, s, o);
    if ((threadIdx.x & 31) == 0) red[threadIdx.x >> 5] = s;
    __syncthreads();
    if (threadIdx.x < 8) {
        float v = red[threadIdx.x];
        #pragma unroll
        for (int o = 4; o; o >>= 1) v += __shfl_xor_sync(0xffu, v, o);
        if (threadIdx.x == 0) red[0] = v;
    }
    __syncthreads();
    float inv = rsqrtf(red[0] / (float)D + EPS);
    for (int i = threadIdx.x * 2; i < D; i += blockDim.x * 2) {
        float a = row[i] * inv * w[i];
        float b = row[i+1] * inv * w[i+1];
        float ha = __bfloat162float(__float2bfloat16(a));
        float hb = __bfloat162float(__float2bfloat16(b));
        ((uint32_t*)hi)[((size_t)t * D + i) >> 1] = pkbf2(a, b);
        ((uint32_t*)lo)[((size_t)t * D + i) >> 1] = pkbf2(a - ha, b - hb);
    }
}

// ---------------- conv + silu -> xi fp32 + bf16 hi/lo ----------------
__global__ void conv_silu_k(const float* __restrict__ xz, const float* __restrict__ cw,
                            const float* __restrict__ cb, float* __restrict__ xi,
                            __nv_bfloat16* __restrict__ hi, __nv_bfloat16* __restrict__ lo) {
    int idx = (blockIdx.x * blockDim.x + threadIdx.x) * 2;
    if (idx >= TOK * DI) return;
    int d = idx % DI; int t = idx / DI; int l = t % LSEQ; int tb = t - l;
    float a0 = cb[d], a1 = cb[d + 1];
    #pragma unroll
    for (int k = 0; k < KCONV; k++) {
        int ls = l + k - (KCONV - 1);
        if (ls >= 0) {
            const float* base = xz + (size_t)(tb + ls) * (2 * DI) + d;
            a0 += base[0] * cw[d * KCONV + k];
            a1 += base[1] * cw[(d + 1) * KCONV + k];
        }
    }
    a0 = a0 / (1.f + __expf(-a0));
    a1 = a1 / (1.f + __expf(-a1));
    *(float2*)(xi + idx) = make_float2(a0, a1);
    float h0 = __bfloat162float(__float2bfloat16(a0));
    float h1 = __bfloat162float(__float2bfloat16(a1));
    ((uint32_t*)hi)[idx >> 1] = pkbf2(a0, a1);
    ((uint32_t*)lo)[idx >> 1] = pkbf2(a0 - h0, a1 - h1);
}

// ---------------- selective scan: smem-staged, fused softplus+gate+bf16 ----
#define SCH 64
__global__ void __launch_bounds__(128) scan_k(
        const float* __restrict__ lA, const float* __restrict__ Dp,
        const float* __restrict__ bcd, const float* __restrict__ draw,
        const float* __restrict__ db, const float* __restrict__ xi,
        const float* __restrict__ xz,
        __nv_bfloat16* __restrict__ yh, __nv_bfloat16* __restrict__ yl) {
    __shared__ float sBC[2][SCH][32];
    __shared__ float sD [2][SCH][8];
    __shared__ float sX [2][SCH][8];
    __shared__ float sR [2][SCH][8];
    int tid = threadIdx.x;
    int ch = tid >> 4, n = tid & 15;
    int b  = blockIdx.x / (DI / 8);
    int d0 = (blockIdx.x % (DI / 8)) * 8;
    int d  = d0 + ch;
    float Av   = -expf(lA[d * NSTATE + n]);
    float invA = 1.f / Av;
    float Dv   = Dp[d];
    float dbv  = db[d];
    const float* bp = bcd  + (size_t)b * LSEQ * BCDW;
    const float* dp = draw + (size_t)b * LSEQ * DI + d0;
    const float* xp = xi   + (size_t)b * LSEQ * DI + d0;
    const float* rp = xz   + (size_t)b * LSEQ * 2 * DI + DI + d0;
    size_t ybase = (size_t)b * LSEQ * DI + d0;

    auto load = [&](int c) {
        if (c < LSEQ / SCH) {
            int buf = c & 1;
            int l0 = c * SCH;
            #pragma unroll
            for (int i = 0; i < 4; i++) {
                int id = tid + i * 128;
                int l = id >> 3, cc = id & 7;
                cp16(s2u(&sBC[buf][l][cc * 4]), bp + (size_t)(l0 + l) * BCDW + cc * 4, 16);
            }
            int l = tid >> 1, hf = (tid & 1) * 4;
            cp16(s2u(&sD[buf][l][hf]), dp + (size_t)(l0 + l) * DI + hf, 16);
            cp16(s2u(&sX[buf][l][hf]), xp + (size_t)(l0 + l) * DI + hf, 16);
            cp16(s2u(&sR[buf][l][hf]), rp + (size_t)(l0 + l) * 2 * DI + hf, 16);
        }
        asm volatile("cp.async.commit_group;" ::: "memory");
    };

    float hs = 0.f;
    load(0); load(1);
    for (int c = 0; c < LSEQ / SCH; c++) {
        asm volatile("cp.async.wait_group 1;" ::: "memory");
        __syncthreads();
        int buf = c & 1;
        int lg = c * SCH;
        #pragma unroll 4
        for (int l = 0; l < SCH; l++) {
            float z  = sD[buf][l][ch] + dbv;
            float dl = (z > 20.f) ? z : log1pf(__expf(z));
            float dA = dl * Av;
            float em = __expf(dA) - 1.f;
            float xv = sX[buf][l][ch];
            float g  = invA * sBC[buf][l][n] * xv;
            hs = fmaf(em + 1.f, hs, em * g);
            float cc = sBC[buf][l][16 + n] * hs;
            cc += __shfl_xor_sync(0xffffffffu, cc, 1);
            cc += __shfl_xor_sync(0xffffffffu, cc, 2);
            cc += __shfl_xor_sync(0xffffffffu, cc, 4);
            cc += __shfl_xor_sync(0xffffffffu, cc, 8);
            if (n == 0) {
                float r  = sR[buf][l][ch];
                float sg = r / (1.f + __expf(-r));
                float yv = (cc + xv * Dv) * sg;
                __nv_bfloat16 hv = __float2bfloat16(yv);
                size_t o = ybase + (size_t)(lg + l) * DI + ch;
                yh[o] = hv;
                yl[o] = __float2bfloat16(yv - __bfloat162float(hv));
            }
        }
        __syncthreads();
        load(c + 2);
    }
}

// ---------------- launch ----------------
extern "C" void kernel_launch(void* const* d_in, const int* in_sizes, int n_in,
                              void* d_out, int out_size) {
    const int*   x        = (const int*)  d_in[0];
    const float* emb      = (const float*)d_in[1];
    const float* rms_w    = (const float*)d_in[2];
    const float* in_w     = (const float*)d_in[3];
    const float* conv_w   = (const float*)d_in[4];
    const float* conv_b   = (const float*)d_in[5];
    const float* lA       = (const float*)d_in[6];
    const float* bcw      = (const float*)d_in[7];
    const float* dup_w    = (const float*)d_in[8];
    const float* dup_b    = (const float*)d_in[9];
    const float* D_param  = (const float*)d_in[10];
    const float* out_w    = (const float*)d_in[11];
    const float* norm_f_w = (const float*)d_in[12];
    float* out = (float*)d_out;

    float *h, *xz, *xi, *bcd, *bcdp, *delta;
    __nv_bfloat16 *eh, *el, *wh, *wl, *ah, *al;
    cudaGetSymbolAddress((void**)&h,    g_h);
    cudaGetSymbolAddress((void**)&xz,   g_xz);
    cudaGetSymbolAddress((void**)&xi,   g_xi);
    cudaGetSymbolAddress((void**)&bcd,  g_bcd);
    cudaGetSymbolAddress((void**)&bcdp, g_bcdp);
    cudaGetSymbolAddress((void**)&delta,g_delta);
    cudaGetSymbolAddress((void**)&eh,   g_eh);
    cudaGetSymbolAddress((void**)&el,   g_el);
    cudaGetSymbolAddress((void**)&wh,   g_wh);
    cudaGetSymbolAddress((void**)&wl,   g_wl);
    cudaGetSymbolAddress((void**)&ah,   g_ah);
    cudaGetSymbolAddress((void**)&al,   g_al);

    const int SMB = GS_STAGES * GS_BYTES;   // 196608
    cudaFuncSetAttribute(gemm_mma, cudaFuncAttributeMaxDynamicSharedMemorySize, SMB);

    #define CVT8(src, dh, dl, rows, K, Kpad, lda, off) \
        cvt8_k<<<((rows)*((Kpad)/8) + 255) / 256, 256>>>(src, dh, dl, rows, K, Kpad, lda, off)

    // launch #4 = first gemm_mma (in_proj) so ncu captures the GEMM
    CVT8(in_w, wh, wl, 2 * DI, D, D, D, 0);
    embed_k<<<TOK, 256>>>(x, emb, h);

    for (int l = 0; l < NL; l++) {
        const float* in_wl = in_w   + (size_t)l * 2 * DI * D;
        const float* cwl   = conv_w + (size_t)l * DI * KCONV;
        const float* cbl   = conv_b + (size_t)l * DI;
        const float* lAl   = lA     + (size_t)l * DI * NSTATE;
        const float* bcwl  = bcw    + (size_t)l * BCDW * DI;
        const float* dwl   = dup_w  + (size_t)l * DI * DR;
        const float* dbl   = dup_b  + (size_t)l * DI;
        const float* Dpl   = D_param + (size_t)l * DI;
        const float* owl   = out_w  + (size_t)l * D * DI;

        rmsnorm_bf_k<<<TOK, 256>>>(h, rms_w + (size_t)l * D, ah, al);
        if (l > 0) CVT8(in_wl, wh, wl, 2 * DI, D, D, D, 0);
        gemm_mma<<<dim3(TOK / 128, (2 * DI) / 256), 256, SMB>>>(ah, al, wh, wl, xz,
                2 * DI, D, D, 2 * DI, 0, 0);
        conv_silu_k<<<(TOK * DI / 2 + 255) / 256, 256>>>(xz, cwl, cbl, xi, ah, al);
        CVT8(bcwl, wh, wl, BCDW, DI, DI, DI, 0);
        // bcd GEMM: deterministic split-K over 8 chunks of 192
        gemm_mma<<<dim3(TOK / 128, 1, BCD_SPLIT), 256, SMB>>>(ah, al, wh, wl, bcdp,
                BCDW, DI, BCD_KCHUNK, BCDW, 0, TOK * BCDW);
        redk<<<(TOK * BCDW + 255) / 256, 256>>>(bcdp, bcd);
        CVT8(bcd, ah, al, TOK, DR, 64, BCDW, 2 * NSTATE);
        CVT8(dwl, wh, wl, DI, DR, 64, DR, 0);
        gemm_mma<<<dim3(TOK / 128, DI / 256), 256, SMB>>>(ah, al, wh, wl, delta,
                DI, 64, 64, DI, 0, 0);
        scan_k<<<BB * (DI / 8), 128>>>(lAl, Dpl, bcd, delta, dbl, xi, xz, ah, al);
        CVT8(owl, wh, wl, D, DI, DI, DI, 0);
        gemm_mma<<<dim3(TOK / 128, D / 256), 256, SMB>>>(ah, al, wh, wl, h,
                D, DI, DI, D, 1, 0);        // accum=1: fused residual
    }

    CVT8(emb, eh, el, VOC, D, D, D, 0);
    rmsnorm_bf_k<<<TOK, 256>>>(h, norm_f_w, ah, al);
    gemm_mma<<<dim3(TOK / 128, VOC / 256), 256, SMB>>>(ah, al, eh, el, out,
            VOC, D, D, VOC, 0, 0);
}

// round 16
// speedup vs baseline: 1.1710x; 1.1710x over previous
#include <cuda_runtime.h>
#include <cuda_bf16.h>
#include <cstdint>

// ---------------- model constants ----------------
#define NL     2
#define D      768
#define DI     1536
#define NSTATE 16
#define DR     48
#define KCONV  4
#define VOC    32000
#define BB     2
#define LSEQ   1024
#define TOK    (BB*LSEQ)        // 2048
#define BCDW   (2*NSTATE+DR)    // 80
#define EPS    1e-5f
#define BCD_SPLIT 8
#define BCD_KCHUNK (DI/BCD_SPLIT)   // 192

// ---------------- scratch ----------------
__device__ __align__(256) float g_h [TOK*D];
__device__ __align__(256) float g_xz[TOK*2*DI];
__device__ __align__(256) float g_xi[TOK*DI];
__device__ __align__(256) float g_bcd[TOK*BCDW];
__device__ __align__(256) float g_bcdp[BCD_SPLIT*TOK*BCDW];
__device__ __align__(256) float g_delta[TOK*DI];
__device__ __align__(256) __nv_bfloat16 g_eh[VOC*D];
__device__ __align__(256) __nv_bfloat16 g_el[VOC*D];
__device__ __align__(256) __nv_bfloat16 g_wh[2*DI*D];
__device__ __align__(256) __nv_bfloat16 g_wl[2*DI*D];
__device__ __align__(256) __nv_bfloat16 g_ah[TOK*DI];
__device__ __align__(256) __nv_bfloat16 g_al[TOK*DI];

// ---------------- helpers ----------------
__device__ __forceinline__ uint32_t s2u(const void* p) {
    uint32_t a;
    asm("{ .reg .u64 t; cvta.to.shared.u64 t, %1; cvt.u32.u64 %0, t; }" : "=r"(a) : "l"(p));
    return a;
}
__device__ __forceinline__ void cp16(uint32_t saddr, const void* gaddr, int sz) {
    asm volatile("cp.async.cg.shared.global [%0], [%1], 16, %2;"
                 :: "r"(saddr), "l"(gaddr), "r"(sz) : "memory");
}
__device__ __forceinline__ void ldmx4(uint32_t* r, uint32_t addr) {
    asm volatile("ldmatrix.sync.aligned.m8n8.x4.shared.b16 {%0,%1,%2,%3}, [%4];"
                 : "=r"(r[0]), "=r"(r[1]), "=r"(r[2]), "=r"(r[3]) : "r"(addr));
}
__device__ __forceinline__ void mma16816(float* c, const uint32_t* a, const uint32_t* b) {
    asm volatile("mma.sync.aligned.m16n8k16.row.col.f32.bf16.bf16.f32 "
                 "{%0,%1,%2,%3}, {%4,%5,%6,%7}, {%8,%9}, {%0,%1,%2,%3};"
                 : "+f"(c[0]), "+f"(c[1]), "+f"(c[2]), "+f"(c[3])
                 : "r"(a[0]), "r"(a[1]), "r"(a[2]), "r"(a[3]), "r"(b[0]), "r"(b[1]));
}
__device__ __forceinline__ uint32_t pkbf2(float a, float b) {
    return (uint32_t)__bfloat16_as_ushort(__float2bfloat16(a))
         | ((uint32_t)__bfloat16_as_ushort(__float2bfloat16(b)) << 16);
}

// ---------------- vectorized bf16 hi/lo split (8 elems / thread) ----------
__global__ void cvt8_k(const float* __restrict__ src, __nv_bfloat16* __restrict__ hi,
                       __nv_bfloat16* __restrict__ lo, int rows, int K, int Kpad,
                       int lda, int off) {
    int cpr = Kpad >> 3;
    int idx = blockIdx.x * blockDim.x + threadIdx.x;
    if (idx >= rows * cpr) return;
    int r = idx / cpr, c = idx - r * cpr;
    int k0 = c << 3;
    float v[8];
    if (k0 + 8 <= K) {
        const float4* p = (const float4*)(src + (size_t)r * lda + off + k0);
        float4 x0 = p[0], x1 = p[1];
        v[0]=x0.x; v[1]=x0.y; v[2]=x0.z; v[3]=x0.w;
        v[4]=x1.x; v[5]=x1.y; v[6]=x1.z; v[7]=x1.w;
    } else {
        #pragma unroll
        for (int j = 0; j < 8; j++)
            v[j] = (k0 + j < K) ? src[(size_t)r * lda + off + k0 + j] : 0.f;
    }
    uint4 hp, lp;
    uint32_t* hq = (uint32_t*)&hp; uint32_t* lq = (uint32_t*)&lp;
    #pragma unroll
    for (int j = 0; j < 4; j++) {
        float a = v[2*j], b = v[2*j+1];
        float ha = __bfloat162float(__float2bfloat16(a));
        float hb = __bfloat162float(__float2bfloat16(b));
        hq[j] = pkbf2(a, b);
        lq[j] = pkbf2(a - ha, b - hb);
    }
    ((uint4*)hi)[idx] = hp;
    ((uint4*)lo)[idx] = lp;
}

// ---------------- HMMA split-bf16 NT GEMM ----------------
// CTA 128x128, 256 threads, warp tile 64x32, BK=64, 3-stage cp.async,
// single barrier per k-iter, fragment double-buffer prefetch across kc.
#define GS_STAGES 3
#define GS_BYTES  65536   // per stage: Ah 16K | Al 16K | Bh 16K | Bl 16K

__global__ void __launch_bounds__(256, 1) gemm_mma(
    const __nv_bfloat16* __restrict__ Ah, const __nv_bfloat16* __restrict__ Al,
    const __nv_bfloat16* __restrict__ Bh, const __nv_bfloat16* __restrict__ Bl,
    float* __restrict__ C, int Nn, int Kpad, int Kloop, int ldc, int accum,
    int partStride) {
    extern __shared__ __align__(1024) char gsm[];
    const uint32_t sb = s2u(gsm);
    const int tid = threadIdx.x, lane = tid & 31, wid = tid >> 5;
    const int bm = blockIdx.x * 128, bn = blockIdx.y * 128;
    const int mw = wid & 1, nw = wid >> 1;     // warp tile: 64(M) x 32(N)
    const int nK = Kloop >> 6;
    const int kOff = blockIdx.z * Kloop;
    C += (size_t)blockIdx.z * partStride;
    const int lr = tid >> 3, lch = tid & 7;

    auto issue = [&](int s) {
        if (s < nK) {
            uint32_t buf = sb + (s % GS_STAGES) * GS_BYTES;
            int kb = kOff + (s << 6);
            #pragma unroll
            for (int q = 0; q < 4; q++) {
                int r = lr + q * 32;
                uint32_t so = (uint32_t)(r * 128 + ((lch ^ (r & 7)) << 4));
                size_t ga = (size_t)(bm + r) * Kpad + kb + (lch << 3);
                cp16(buf + so,         Ah + ga, 16);
                cp16(buf + 16384 + so, Al + ga, 16);
                int rb = bn + r;
                int sz = (rb < Nn) ? 16 : 0;
                size_t gb = (size_t)((rb < Nn) ? rb : 0) * Kpad + kb + (lch << 3);
                cp16(buf + 32768 + so, Bh + gb, sz);
                cp16(buf + 49152 + so, Bl + gb, sz);
            }
        }
        asm volatile("cp.async.commit_group;" ::: "memory");
    };

    float acc[4][4][4];
    #pragma unroll
    for (int i = 0; i < 4; i++)
        #pragma unroll
        for (int j = 0; j < 4; j++)
            #pragma unroll
            for (int v = 0; v < 4; v++) acc[i][j][v] = 0.f;

    const int lrow8 = (lane & 7) + ((lane >> 3) & 1) * 8;
    const int lkh   = lane >> 4;

    // double-buffered fragments
    uint32_t fah[2][4][4], fal[2][4][4], fbh[2][4][2], fbl[2][4][2];

    auto ldfrag = [&](uint32_t base, int kc, int slot) {
        int cc = kc * 2 + lkh;
        #pragma unroll
        for (int ma = 0; ma < 4; ma++) {
            int r = mw * 64 + ma * 16 + lrow8;
            uint32_t ad = base + r * 128 + ((cc ^ (r & 7)) << 4);
            ldmx4(fah[slot][ma], ad);
            ldmx4(fal[slot][ma], ad + 16384);
        }
        #pragma unroll
        for (int nb = 0; nb < 2; nb++) {
            int r = nw * 32 + nb * 16 + lrow8;
            uint32_t bd = base + 32768 + r * 128 + ((cc ^ (r & 7)) << 4);
            uint32_t t[4];
            ldmx4(t, bd);
            fbh[slot][nb*2][0]=t[0]; fbh[slot][nb*2+1][0]=t[1];
            fbh[slot][nb*2][1]=t[2]; fbh[slot][nb*2+1][1]=t[3];
            ldmx4(t, bd + 16384);
            fbl[slot][nb*2][0]=t[0]; fbl[slot][nb*2+1][0]=t[1];
            fbl[slot][nb*2][1]=t[2]; fbl[slot][nb*2+1][1]=t[3];
        }
    };

    #pragma unroll
    for (int s = 0; s < GS_STAGES - 1; s++) issue(s);

    for (int it = 0; it < nK; ++it) {
        asm volatile("cp.async.wait_group %0;" :: "n"(GS_STAGES - 2) : "memory");
        __syncthreads();
        uint32_t base = sb + (it % GS_STAGES) * GS_BYTES;
        ldfrag(base, 0, 0);
        #pragma unroll
        for (int kc = 0; kc < 4; kc++) {
            int cur = kc & 1;
            if (kc < 3) ldfrag(base, kc + 1, cur ^ 1);
            // term-major: 16 independent accumulators between same-acc reuse
            #pragma unroll
            for (int ma = 0; ma < 4; ma++)
                #pragma unroll
                for (int na = 0; na < 4; na++)
                    mma16816(acc[ma][na], fah[cur][ma], fbh[cur][na]);
            #pragma unroll
            for (int ma = 0; ma < 4; ma++)
                #pragma unroll
                for (int na = 0; na < 4; na++)
                    mma16816(acc[ma][na], fah[cur][ma], fbl[cur][na]);
            #pragma unroll
            for (int ma = 0; ma < 4; ma++)
                #pragma unroll
                for (int na = 0; na < 4; na++)
                    mma16816(acc[ma][na], fal[cur][ma], fbh[cur][na]);
        }
        issue(it + GS_STAGES - 1);
    }

    // epilogue
    #pragma unroll
    for (int ma = 0; ma < 4; ma++) {
        int row0 = bm + mw * 64 + ma * 16 + (lane >> 2);
        #pragma unroll
        for (int na = 0; na < 4; na++) {
            int col = bn + nw * 32 + na * 8 + (lane & 3) * 2;
            if (col < Nn) {
                float* p0 = C + (size_t)row0 * ldc + col;
                float* p1 = C + (size_t)(row0 + 8) * ldc + col;
                float2 v0 = make_float2(acc[ma][na][0], acc[ma][na][1]);
                float2 v1 = make_float2(acc[ma][na][2], acc[ma][na][3]);
                if (accum) {
                    float2 o0 = *(float2*)p0, o1 = *(float2*)p1;
                    v0.x += o0.x; v0.y += o0.y; v1.x += o1.x; v1.y += o1.y;
                }
                *(float2*)p0 = v0;
                *(float2*)p1 = v1;
            }
        }
    }
}

// ---------------- split-K reduce (fixed order -> deterministic) ------------
__global__ void redk(const float* __restrict__ part, float* __restrict__ outp) {
    int i = blockIdx.x * blockDim.x + threadIdx.x;
    if (i >= TOK * BCDW) return;
    float s = 0.f;
    #pragma unroll
    for (int z = 0; z < BCD_SPLIT; z++) s += part[(size_t)z * TOK * BCDW + i];
    outp[i] = s;
}

// ---------------- embedding gather ----------------
__global__ void embed_k(const int* __restrict__ x, const float* __restrict__ emb,
                        float* __restrict__ h) {
    int t = blockIdx.x;
    int v = x[t];
    const float4* src = (const float4*)(emb + (size_t)v * D);
    float4* dst = (float4*)(h + (size_t)t * D);
    for (int i = threadIdx.x; i < D / 4; i += blockDim.x) dst[i] = src[i];
}

// ---------------- rmsnorm -> bf16 hi/lo ----------------
__global__ void rmsnorm_bf_k(const float* __restrict__ in, const float* __restrict__ w,
                             __nv_bfloat16* __restrict__ hi, __nv_bfloat16* __restrict__ lo) {
    int t = blockIdx.x;
    const float* row = in + (size_t)t * D;
    float s = 0.f;
    for (int i = threadIdx.x; i < D; i += blockDim.x) { float v = row[i]; s += v * v; }
    __shared__ float red[8];
    #pragma unroll
    for (int o = 16; o; o >>= 1) s += __shfl_xor_sync(0xffffffffu, s, o);
    if ((threadIdx.x & 31) == 0) red[threadIdx.x >> 5] = s;
    __syncthreads();
    if (threadIdx.x < 8) {
        float v = red[threadIdx.x];
        #pragma unroll
        for (int o = 4; o; o >>= 1) v += __shfl_xor_sync(0xffu, v, o);
        if (threadIdx.x == 0) red[0] = v;
    }
    __syncthreads();
    float inv = rsqrtf(red[0] / (float)D + EPS);
    for (int i = threadIdx.x * 2; i < D; i += blockDim.x * 2) {
        float a = row[i] * inv * w[i];
        float b = row[i+1] * inv * w[i+1];
        float ha = __bfloat162float(__float2bfloat16(a));
        float hb = __bfloat162float(__float2bfloat16(b));
        ((uint32_t*)hi)[((size_t)t * D + i) >> 1] = pkbf2(a, b);
        ((uint32_t*)lo)[((size_t)t * D + i) >> 1] = pkbf2(a - ha, b - hb);
    }
}

// ---------------- conv + silu -> xi fp32 + bf16 hi/lo ----------------
__global__ void conv_silu_k(const float* __restrict__ xz, const float* __restrict__ cw,
                            const float* __restrict__ cb, float* __restrict__ xi,
                            __nv_bfloat16* __restrict__ hi, __nv_bfloat16* __restrict__ lo) {
    int idx = (blockIdx.x * blockDim.x + threadIdx.x) * 2;
    if (idx >= TOK * DI) return;
    int d = idx % DI; int t = idx / DI; int l = t % LSEQ; int tb = t - l;
    float a0 = cb[d], a1 = cb[d + 1];
    #pragma unroll
    for (int k = 0; k < KCONV; k++) {
        int ls = l + k - (KCONV - 1);
        if (ls >= 0) {
            const float* base = xz + (size_t)(tb + ls) * (2 * DI) + d;
            a0 += base[0] * cw[d * KCONV + k];
            a1 += base[1] * cw[(d + 1) * KCONV + k];
        }
    }
    a0 = a0 / (1.f + __expf(-a0));
    a1 = a1 / (1.f + __expf(-a1));
    *(float2*)(xi + idx) = make_float2(a0, a1);
    float h0 = __bfloat162float(__float2bfloat16(a0));
    float h1 = __bfloat162float(__float2bfloat16(a1));
    ((uint32_t*)hi)[idx >> 1] = pkbf2(a0, a1);
    ((uint32_t*)lo)[idx >> 1] = pkbf2(a0 - h0, a1 - h1);
}

// ---------------- selective scan: smem-staged, fused softplus+gate+bf16 ----
#define SCH 64
__global__ void __launch_bounds__(128) scan_k(
        const float* __restrict__ lA, const float* __restrict__ Dp,
        const float* __restrict__ bcd, const float* __restrict__ draw,
        const float* __restrict__ db, const float* __restrict__ xi,
        const float* __restrict__ xz,
        __nv_bfloat16* __restrict__ yh, __nv_bfloat16* __restrict__ yl) {
    __shared__ float sBC[2][SCH][32];
    __shared__ float sD [2][SCH][8];
    __shared__ float sX [2][SCH][8];
    __shared__ float sR [2][SCH][8];
    int tid = threadIdx.x;
    int ch = tid >> 4, n = tid & 15;
    int b  = blockIdx.x / (DI / 8);
    int d0 = (blockIdx.x % (DI / 8)) * 8;
    int d  = d0 + ch;
    float Av   = -expf(lA[d * NSTATE + n]);
    float invA = 1.f / Av;
    float Dv   = Dp[d];
    float dbv  = db[d];
    const float* bp = bcd  + (size_t)b * LSEQ * BCDW;
    const float* dp = draw + (size_t)b * LSEQ * DI + d0;
    const float* xp = xi   + (size_t)b * LSEQ * DI + d0;
    const float* rp = xz   + (size_t)b * LSEQ * 2 * DI + DI + d0;
    size_t ybase = (size_t)b * LSEQ * DI + d0;

    auto load = [&](int c) {
        if (c < LSEQ / SCH) {
            int buf = c & 1;
            int l0 = c * SCH;
            #pragma unroll
            for (int i = 0; i < 4; i++) {
                int id = tid + i * 128;
                int l = id >> 3, cc = id & 7;
                cp16(s2u(&sBC[buf][l][cc * 4]), bp + (size_t)(l0 + l) * BCDW + cc * 4, 16);
            }
            int l = tid >> 1, hf = (tid & 1) * 4;
            cp16(s2u(&sD[buf][l][hf]), dp + (size_t)(l0 + l) * DI + hf, 16);
            cp16(s2u(&sX[buf][l][hf]), xp + (size_t)(l0 + l) * DI + hf, 16);
            cp16(s2u(&sR[buf][l][hf]), rp + (size_t)(l0 + l) * 2 * DI + hf, 16);
        }
        asm volatile("cp.async.commit_group;" ::: "memory");
    };

    float hs = 0.f;
    load(0); load(1);
    for (int c = 0; c < LSEQ / SCH; c++) {
        asm volatile("cp.async.wait_group 1;" ::: "memory");
        __syncthreads();
        int buf = c & 1;
        int lg = c * SCH;
        #pragma unroll 4
        for (int l = 0; l < SCH; l++) {
            float z  = sD[buf][l][ch] + dbv;
            float dl = (z > 20.f) ? z : log1pf(__expf(z));
            float dA = dl * Av;
            float em = __expf(dA) - 1.f;
            float xv = sX[buf][l][ch];
            float g  = invA * sBC[buf][l][n] * xv;
            hs = fmaf(em + 1.f, hs, em * g);
            float cc = sBC[buf][l][16 + n] * hs;
            cc += __shfl_xor_sync(0xffffffffu, cc, 1);
            cc += __shfl_xor_sync(0xffffffffu, cc, 2);
            cc += __shfl_xor_sync(0xffffffffu, cc, 4);
            cc += __shfl_xor_sync(0xffffffffu, cc, 8);
            if (n == 0) {
                float r  = sR[buf][l][ch];
                float sg = r / (1.f + __expf(-r));
                float yv = (cc + xv * Dv) * sg;
                __nv_bfloat16 hv = __float2bfloat16(yv);
                size_t o = ybase + (size_t)(lg + l) * DI + ch;
                yh[o] = hv;
                yl[o] = __float2bfloat16(yv - __bfloat162float(hv));
            }
        }
        __syncthreads();
        load(c + 2);
    }
}

// ---------------- launch ----------------
extern "C" void kernel_launch(void* const* d_in, const int* in_sizes, int n_in,
                              void* d_out, int out_size) {
    const int*   x        = (const int*)  d_in[0];
    const float* emb      = (const float*)d_in[1];
    const float* rms_w    = (const float*)d_in[2];
    const float* in_w     = (const float*)d_in[3];
    const float* conv_w   = (const float*)d_in[4];
    const float* conv_b   = (const float*)d_in[5];
    const float* lA       = (const float*)d_in[6];
    const float* bcw      = (const float*)d_in[7];
    const float* dup_w    = (const float*)d_in[8];
    const float* dup_b    = (const float*)d_in[9];
    const float* D_param  = (const float*)d_in[10];
    const float* out_w    = (const float*)d_in[11];
    const float* norm_f_w = (const float*)d_in[12];
    float* out = (float*)d_out;

    float *h, *xz, *xi, *bcd, *bcdp, *delta;
    __nv_bfloat16 *eh, *el, *wh, *wl, *ah, *al;
    cudaGetSymbolAddress((void**)&h,    g_h);
    cudaGetSymbolAddress((void**)&xz,   g_xz);
    cudaGetSymbolAddress((void**)&xi,   g_xi);
    cudaGetSymbolAddress((void**)&bcd,  g_bcd);
    cudaGetSymbolAddress((void**)&bcdp, g_bcdp);
    cudaGetSymbolAddress((void**)&delta,g_delta);
    cudaGetSymbolAddress((void**)&eh,   g_eh);
    cudaGetSymbolAddress((void**)&el,   g_el);
    cudaGetSymbolAddress((void**)&wh,   g_wh);
    cudaGetSymbolAddress((void**)&wl,   g_wl);
    cudaGetSymbolAddress((void**)&ah,   g_ah);
    cudaGetSymbolAddress((void**)&al,   g_al);

    const int SMB = GS_STAGES * GS_BYTES;   // 196608
    cudaFuncSetAttribute(gemm_mma, cudaFuncAttributeMaxDynamicSharedMemorySize, SMB);

    #define CVT8(src, dh, dl, rows, K, Kpad, lda, off) \
        cvt8_k<<<((rows)*((Kpad)/8) + 255) / 256, 256>>>(src, dh, dl, rows, K, Kpad, lda, off)

    // launch #4 = first gemm_mma (in_proj) so ncu captures the GEMM
    CVT8(in_w, wh, wl, 2 * DI, D, D, D, 0);
    embed_k<<<TOK, 256>>>(x, emb, h);

    for (int l = 0; l < NL; l++) {
        const float* in_wl = in_w   + (size_t)l * 2 * DI * D;
        const float* cwl   = conv_w + (size_t)l * DI * KCONV;
        const float* cbl   = conv_b + (size_t)l * DI;
        const float* lAl   = lA     + (size_t)l * DI * NSTATE;
        const float* bcwl  = bcw    + (size_t)l * BCDW * DI;
        const float* dwl   = dup_w  + (size_t)l * DI * DR;
        const float* dbl   = dup_b  + (size_t)l * DI;
        const float* Dpl   = D_param + (size_t)l * DI;
        const float* owl   = out_w  + (size_t)l * D * DI;

        rmsnorm_bf_k<<<TOK, 256>>>(h, rms_w + (size_t)l * D, ah, al);
        if (l > 0) CVT8(in_wl, wh, wl, 2 * DI, D, D, D, 0);
        gemm_mma<<<dim3(TOK / 128, (2 * DI) / 128), 256, SMB>>>(ah, al, wh, wl, xz,
                2 * DI, D, D, 2 * DI, 0, 0);
        conv_silu_k<<<(TOK * DI / 2 + 255) / 256, 256>>>(xz, cwl, cbl, xi, ah, al);
        CVT8(bcwl, wh, wl, BCDW, DI, DI, DI, 0);
        // bcd GEMM: deterministic split-K over 8 chunks of 192
        gemm_mma<<<dim3(TOK / 128, 1, BCD_SPLIT), 256, SMB>>>(ah, al, wh, wl, bcdp,
                BCDW, DI, BCD_KCHUNK, BCDW, 0, TOK * BCDW);
        redk<<<(TOK * BCDW + 255) / 256, 256>>>(bcdp, bcd);
        CVT8(bcd, ah, al, TOK, DR, 64, BCDW, 2 * NSTATE);
        CVT8(dwl, wh, wl, DI, DR, 64, DR, 0);
        gemm_mma<<<dim3(TOK / 128, DI / 128), 256, SMB>>>(ah, al, wh, wl, delta,
                DI, 64, 64, DI, 0, 0);
        scan_k<<<BB * (DI / 8), 128>>>(lAl, Dpl, bcd, delta, dbl, xi, xz, ah, al);
        CVT8(owl, wh, wl, D, DI, DI, DI, 0);
        gemm_mma<<<dim3(TOK / 128, D / 128), 256, SMB>>>(ah, al, wh, wl, h,
                D, DI, DI, D, 1, 0);        // accum=1: fused residual
    }

    CVT8(emb, eh, el, VOC, D, D, D, 0);
    rmsnorm_bf_k<<<TOK, 256>>>(h, norm_f_w, ah, al);
    gemm_mma<<<dim3(TOK / 128, VOC / 128), 256, SMB>>>(ah, al, eh, el, out,
            VOC, D, D, VOC, 0, 0);
}

// round 17
// speedup vs baseline: 1.3956x; 1.1918x over previous
#include <cuda_runtime.h>
#include <cuda_fp16.h>
#include <cstdint>

// ---------------- model constants ----------------
#define NL     2
#define D      768
#define DI     1536
#define NSTATE 16
#define DR     48
#define KCONV  4
#define VOC    32000
#define BB     2
#define LSEQ   1024
#define TOK    (BB*LSEQ)        // 2048
#define BCDW   (2*NSTATE+DR)    // 80
#define EPS    1e-5f
#define BCD_SPLIT 8
#define BCD_KCHUNK (DI/BCD_SPLIT)   // 192

// ---------------- scratch ----------------
__device__ __align__(256) float g_h [TOK*D];
__device__ __align__(256) float g_xz[TOK*2*DI];
__device__ __align__(256) float g_xi[TOK*DI];
__device__ __align__(256) float g_bcd[TOK*BCDW];
__device__ __align__(256) float g_bcdp[BCD_SPLIT*TOK*BCDW];
__device__ __align__(256) float g_delta[TOK*DI];
__device__ __align__(256) __half g_eh[VOC*D];
__device__ __align__(256) __half g_el[VOC*D];
__device__ __align__(256) __half g_wh[2*DI*D];
__device__ __align__(256) __half g_wl[2*DI*D];
__device__ __align__(256) __half g_ah[TOK*DI];
__device__ __align__(256) __half g_al[TOK*DI];

// ---------------- helpers ----------------
__device__ __forceinline__ uint32_t s2u(const void* p) {
    uint32_t a;
    asm("{ .reg .u64 t; cvta.to.shared.u64 t, %1; cvt.u32.u64 %0, t; }" : "=r"(a) : "l"(p));
    return a;
}
__device__ __forceinline__ void cp16(uint32_t saddr, const void* gaddr, int sz) {
    asm volatile("cp.async.cg.shared.global [%0], [%1], 16, %2;"
                 :: "r"(saddr), "l"(gaddr), "r"(sz) : "memory");
}
__device__ __forceinline__ void ldmx4(uint32_t* r, uint32_t addr) {
    asm volatile("ldmatrix.sync.aligned.m8n8.x4.shared.b16 {%0,%1,%2,%3}, [%4];"
                 : "=r"(r[0]), "=r"(r[1]), "=r"(r[2]), "=r"(r[3]) : "r"(addr));
}
__device__ __forceinline__ void mma16816(float* c, const uint32_t* a, const uint32_t* b) {
    asm volatile("mma.sync.aligned.m16n8k16.row.col.f32.f16.f16.f32 "
                 "{%0,%1,%2,%3}, {%4,%5,%6,%7}, {%8,%9}, {%0,%1,%2,%3};"
                 : "+f"(c[0]), "+f"(c[1]), "+f"(c[2]), "+f"(c[3])
                 : "r"(a[0]), "r"(a[1]), "r"(a[2]), "r"(a[3]), "r"(b[0]), "r"(b[1]));
}
__device__ __forceinline__ uint32_t pkhf2(float a, float b) {
    __half2 h = __floats2half2_rn(a, b);
    return *(uint32_t*)&h;
}

// ---------------- vectorized fp16 hi/lo split (8 elems / thread) ----------
__global__ void cvt8_k(const float* __restrict__ src, __half* __restrict__ hi,
                       __half* __restrict__ lo, int rows, int K, int Kpad,
                       int lda, int off) {
    int cpr = Kpad >> 3;
    int idx = blockIdx.x * blockDim.x + threadIdx.x;
    if (idx >= rows * cpr) return;
    int r = idx / cpr, c = idx - r * cpr;
    int k0 = c << 3;
    float v[8];
    if (k0 + 8 <= K) {
        const float4* p = (const float4*)(src + (size_t)r * lda + off + k0);
        float4 x0 = p[0], x1 = p[1];
        v[0]=x0.x; v[1]=x0.y; v[2]=x0.z; v[3]=x0.w;
        v[4]=x1.x; v[5]=x1.y; v[6]=x1.z; v[7]=x1.w;
    } else {
        #pragma unroll
        for (int j = 0; j < 8; j++)
            v[j] = (k0 + j < K) ? src[(size_t)r * lda + off + k0 + j] : 0.f;
    }
    uint4 hp, lp;
    uint32_t* hq = (uint32_t*)&hp; uint32_t* lq = (uint32_t*)&lp;
    #pragma unroll
    for (int j = 0; j < 4; j++) {
        float a = v[2*j], b = v[2*j+1];
        float ha = __half2float(__float2half_rn(a));
        float hb = __half2float(__float2half_rn(b));
        hq[j] = pkhf2(a, b);
        lq[j] = pkhf2(a - ha, b - hb);
    }
    ((uint4*)hi)[idx] = hp;
    ((uint4*)lo)[idx] = lp;
}

// ---------------- HMMA fp16 2-product NT GEMM ----------------
// C = (Ah+Al) * Bh^T, fp32 accum.  CTA 128x128, warp 64x32, BK=64,
// 3-stage cp.async, single barrier/k-iter, fragment double-buffer prefetch.
#define GS_STAGES 3
#define GS_BYTES  49152   // per stage: Ah 16K | Al 16K | Bh 16K

__global__ void __launch_bounds__(256, 1) gemm_mma(
    const __half* __restrict__ Ah, const __half* __restrict__ Al,
    const __half* __restrict__ Bh,
    float* __restrict__ C, int Nn, int Kpad, int Kloop, int ldc, int accum,
    int partStride) {
    extern __shared__ __align__(1024) char gsm[];
    const uint32_t sb = s2u(gsm);
    const int tid = threadIdx.x, lane = tid & 31, wid = tid >> 5;
    const int bm = blockIdx.x * 128, bn = blockIdx.y * 128;
    const int mw = wid & 1, nw = wid >> 1;     // warp tile: 64(M) x 32(N)
    const int nK = Kloop >> 6;
    const int kOff = blockIdx.z * Kloop;
    C += (size_t)blockIdx.z * partStride;
    const int lr = tid >> 3, lch = tid & 7;

    auto issue = [&](int s) {
        if (s < nK) {
            uint32_t buf = sb + (s % GS_STAGES) * GS_BYTES;
            int kb = kOff + (s << 6);
            #pragma unroll
            for (int q = 0; q < 4; q++) {
                int r = lr + q * 32;
                uint32_t so = (uint32_t)(r * 128 + ((lch ^ (r & 7)) << 4));
                size_t ga = (size_t)(bm + r) * Kpad + kb + (lch << 3);
                cp16(buf + so,         Ah + ga, 16);
                cp16(buf + 16384 + so, Al + ga, 16);
                int rb = bn + r;
                int sz = (rb < Nn) ? 16 : 0;
                size_t gb = (size_t)((rb < Nn) ? rb : 0) * Kpad + kb + (lch << 3);
                cp16(buf + 32768 + so, Bh + gb, sz);
            }
        }
        asm volatile("cp.async.commit_group;" ::: "memory");
    };

    float acc[4][4][4];
    #pragma unroll
    for (int i = 0; i < 4; i++)
        #pragma unroll
        for (int j = 0; j < 4; j++)
            #pragma unroll
            for (int v = 0; v < 4; v++) acc[i][j][v] = 0.f;

    const int lrow8 = (lane & 7) + ((lane >> 3) & 1) * 8;
    const int lkh   = lane >> 4;

    // double-buffered fragments
    uint32_t fah[2][4][4], fal[2][4][4], fbh[2][4][2];

    auto ldfrag = [&](uint32_t base, int kc, int slot) {
        int cc = kc * 2 + lkh;
        #pragma unroll
        for (int ma = 0; ma < 4; ma++) {
            int r = mw * 64 + ma * 16 + lrow8;
            uint32_t ad = base + r * 128 + ((cc ^ (r & 7)) << 4);
            ldmx4(fah[slot][ma], ad);
            ldmx4(fal[slot][ma], ad + 16384);
        }
        #pragma unroll
        for (int nb = 0; nb < 2; nb++) {
            int r = nw * 32 + nb * 16 + lrow8;
            uint32_t bd = base + 32768 + r * 128 + ((cc ^ (r & 7)) << 4);
            uint32_t t[4];
            ldmx4(t, bd);
            fbh[slot][nb*2][0]=t[0]; fbh[slot][nb*2+1][0]=t[1];
            fbh[slot][nb*2][1]=t[2]; fbh[slot][nb*2+1][1]=t[3];
        }
    };

    #pragma unroll
    for (int s = 0; s < GS_STAGES - 1; s++) issue(s);

    for (int it = 0; it < nK; ++it) {
        asm volatile("cp.async.wait_group %0;" :: "n"(GS_STAGES - 2) : "memory");
        __syncthreads();
        uint32_t base = sb + (it % GS_STAGES) * GS_BYTES;
        ldfrag(base, 0, 0);
        #pragma unroll
        for (int kc = 0; kc < 4; kc++) {
            int cur = kc & 1;
            if (kc < 3) ldfrag(base, kc + 1, cur ^ 1);
            #pragma unroll
            for (int ma = 0; ma < 4; ma++)
                #pragma unroll
                for (int na = 0; na < 4; na++)
                    mma16816(acc[ma][na], fah[cur][ma], fbh[cur][na]);
            #pragma unroll
            for (int ma = 0; ma < 4; ma++)
                #pragma unroll
                for (int na = 0; na < 4; na++)
                    mma16816(acc[ma][na], fal[cur][ma], fbh[cur][na]);
        }
        issue(it + GS_STAGES - 1);
    }

    // epilogue
    #pragma unroll
    for (int ma = 0; ma < 4; ma++) {
        int row0 = bm + mw * 64 + ma * 16 + (lane >> 2);
        #pragma unroll
        for (int na = 0; na < 4; na++) {
            int col = bn + nw * 32 + na * 8 + (lane & 3) * 2;
            if (col < Nn) {
                float* p0 = C + (size_t)row0 * ldc + col;
                float* p1 = C + (size_t)(row0 + 8) * ldc + col;
                float2 v0 = make_float2(acc[ma][na][0], acc[ma][na][1]);
                float2 v1 = make_float2(acc[ma][na][2], acc[ma][na][3]);
                if (accum) {
                    float2 o0 = *(float2*)p0, o1 = *(float2*)p1;
                    v0.x += o0.x; v0.y += o0.y; v1.x += o1.x; v1.y += o1.y;
                }
                *(float2*)p0 = v0;
                *(float2*)p1 = v1;
            }
        }
    }
}

// ---------------- split-K reduce (fixed order -> deterministic) ------------
__global__ void redk(const float* __restrict__ part, float* __restrict__ outp) {
    int i = blockIdx.x * blockDim.x + threadIdx.x;
    if (i >= TOK * BCDW) return;
    float s = 0.f;
    #pragma unroll
    for (int z = 0; z < BCD_SPLIT; z++) s += part[(size_t)z * TOK * BCDW + i];
    outp[i] = s;
}

// ---------------- embedding gather ----------------
__global__ void embed_k(const int* __restrict__ x, const float* __restrict__ emb,
                        float* __restrict__ h) {
    int t = blockIdx.x;
    int v = x[t];
    const float4* src = (const float4*)(emb + (size_t)v * D);
    float4* dst = (float4*)(h + (size_t)t * D);
    for (int i = threadIdx.x; i < D / 4; i += blockDim.x) dst[i] = src[i];
}

// ---------------- rmsnorm -> fp16 hi/lo ----------------
__global__ void rmsnorm_bf_k(const float* __restrict__ in, const float* __restrict__ w,
                             __half* __restrict__ hi, __half* __restrict__ lo) {
    int t = blockIdx.x;
    const float* row = in + (size_t)t * D;
    float s = 0.f;
    for (int i = threadIdx.x; i < D; i += blockDim.x) { float v = row[i]; s += v * v; }
    __shared__ float red[8];
    #pragma unroll
    for (int o = 16; o; o >>= 1) s += __shfl_xor_sync(0xffffffffu, s, o);
    if ((threadIdx.x & 31) == 0) red[threadIdx.x >> 5] = s;
    __syncthreads();
    if (threadIdx.x < 8) {
        float v = red[threadIdx.x];
        #pragma unroll
        for (int o = 4; o; o >>= 1) v += __shfl_xor_sync(0xffu, v, o);
        if (threadIdx.x == 0) red[0] = v;
    }
    __syncthreads();
    float inv = rsqrtf(red[0] / (float)D + EPS);
    for (int i = threadIdx.x * 2; i < D; i += blockDim.x * 2) {
        float a = row[i] * inv * w[i];
        float b = row[i+1] * inv * w[i+1];
        float ha = __half2float(__float2half_rn(a));
        float hb = __half2float(__float2half_rn(b));
        ((uint32_t*)hi)[((size_t)t * D + i) >> 1] = pkhf2(a, b);
        ((uint32_t*)lo)[((size_t)t * D + i) >> 1] = pkhf2(a - ha, b - hb);
    }
}

// ---------------- conv + silu -> xi fp32 + fp16 hi/lo ----------------
__global__ void conv_silu_k(const float* __restrict__ xz, const float* __restrict__ cw,
                            const float* __restrict__ cb, float* __restrict__ xi,
                            __half* __restrict__ hi, __half* __restrict__ lo) {
    int idx = (blockIdx.x * blockDim.x + threadIdx.x) * 2;
    if (idx >= TOK * DI) return;
    int d = idx % DI; int t = idx / DI; int l = t % LSEQ; int tb = t - l;
    float a0 = cb[d], a1 = cb[d + 1];
    #pragma unroll
    for (int k = 0; k < KCONV; k++) {
        int ls = l + k - (KCONV - 1);
        if (ls >= 0) {
            const float* base = xz + (size_t)(tb + ls) * (2 * DI) + d;
            a0 += base[0] * cw[d * KCONV + k];
            a1 += base[1] * cw[(d + 1) * KCONV + k];
        }
    }
    a0 = a0 / (1.f + __expf(-a0));
    a1 = a1 / (1.f + __expf(-a1));
    *(float2*)(xi + idx) = make_float2(a0, a1);
    float h0 = __half2float(__float2half_rn(a0));
    float h1 = __half2float(__float2half_rn(a1));
    ((uint32_t*)hi)[idx >> 1] = pkhf2(a0, a1);
    ((uint32_t*)lo)[idx >> 1] = pkhf2(a0 - h0, a1 - h1);
}

// ---------------- selective scan: smem-staged, fused softplus+gate+fp16 ----
#define SCH 64
__global__ void __launch_bounds__(128) scan_k(
        const float* __restrict__ lA, const float* __restrict__ Dp,
        const float* __restrict__ bcd, const float* __restrict__ draw,
        const float* __restrict__ db, const float* __restrict__ xi,
        const float* __restrict__ xz,
        __half* __restrict__ yh, __half* __restrict__ yl) {
    __shared__ float sBC[2][SCH][32];
    __shared__ float sD [2][SCH][8];
    __shared__ float sX [2][SCH][8];
    __shared__ float sR [2][SCH][8];
    int tid = threadIdx.x;
    int ch = tid >> 4, n = tid & 15;
    int b  = blockIdx.x / (DI / 8);
    int d0 = (blockIdx.x % (DI / 8)) * 8;
    int d  = d0 + ch;
    float Av   = -expf(lA[d * NSTATE + n]);
    float invA = 1.f / Av;
    float Dv   = Dp[d];
    float dbv  = db[d];
    const float* bp = bcd  + (size_t)b * LSEQ * BCDW;
    const float* dp = draw + (size_t)b * LSEQ * DI + d0;
    const float* xp = xi   + (size_t)b * LSEQ * DI + d0;
    const float* rp = xz   + (size_t)b * LSEQ * 2 * DI + DI + d0;
    size_t ybase = (size_t)b * LSEQ * DI + d0;

    auto load = [&](int c) {
        if (c < LSEQ / SCH) {
            int buf = c & 1;
            int l0 = c * SCH;
            #pragma unroll
            for (int i = 0; i < 4; i++) {
                int id = tid + i * 128;
                int l = id >> 3, cc = id & 7;
                cp16(s2u(&sBC[buf][l][cc * 4]), bp + (size_t)(l0 + l) * BCDW + cc * 4, 16);
            }
            int l = tid >> 1, hf = (tid & 1) * 4;
            cp16(s2u(&sD[buf][l][hf]), dp + (size_t)(l0 + l) * DI + hf, 16);
            cp16(s2u(&sX[buf][l][hf]), xp + (size_t)(l0 + l) * DI + hf, 16);
            cp16(s2u(&sR[buf][l][hf]), rp + (size_t)(l0 + l) * 2 * DI + hf, 16);
        }
        asm volatile("cp.async.commit_group;" ::: "memory");
    };

    float hs = 0.f;
    load(0); load(1);
    for (int c = 0; c < LSEQ / SCH; c++) {
        asm volatile("cp.async.wait_group 1;" ::: "memory");
        __syncthreads();
        int buf = c & 1;
        int lg = c * SCH;
        #pragma unroll 4
        for (int l = 0; l < SCH; l++) {
            float z  = sD[buf][l][ch] + dbv;
            float dl = (z > 20.f) ? z : log1pf(__expf(z));
            float dA = dl * Av;
            float em = __expf(dA) - 1.f;
            float xv = sX[buf][l][ch];
            float g  = invA * sBC[buf][l][n] * xv;
            hs = fmaf(em + 1.f, hs, em * g);
            float cc = sBC[buf][l][16 + n] * hs;
            cc += __shfl_xor_sync(0xffffffffu, cc, 1);
            cc += __shfl_xor_sync(0xffffffffu, cc, 2);
            cc += __shfl_xor_sync(0xffffffffu, cc, 4);
            cc += __shfl_xor_sync(0xffffffffu, cc, 8);
            if (n == 0) {
                float r  = sR[buf][l][ch];
                float sg = r / (1.f + __expf(-r));
                float yv = (cc + xv * Dv) * sg;
                float hv = __half2float(__float2half_rn(yv));
                size_t o = ybase + (size_t)(lg + l) * DI + ch;
                yh[o] = __float2half_rn(yv);
                yl[o] = __float2half_rn(yv - hv);
            }
        }
        __syncthreads();
        load(c + 2);
    }
}

// ---------------- launch ----------------
extern "C" void kernel_launch(void* const* d_in, const int* in_sizes, int n_in,
                              void* d_out, int out_size) {
    const int*   x        = (const int*)  d_in[0];
    const float* emb      = (const float*)d_in[1];
    const float* rms_w    = (const float*)d_in[2];
    const float* in_w     = (const float*)d_in[3];
    const float* conv_w   = (const float*)d_in[4];
    const float* conv_b   = (const float*)d_in[5];
    const float* lA       = (const float*)d_in[6];
    const float* bcw      = (const float*)d_in[7];
    const float* dup_w    = (const float*)d_in[8];
    const float* dup_b    = (const float*)d_in[9];
    const float* D_param  = (const float*)d_in[10];
    const float* out_w    = (const float*)d_in[11];
    const float* norm_f_w = (const float*)d_in[12];
    float* out = (float*)d_out;

    float *h, *xz, *xi, *bcd, *bcdp, *delta;
    __half *eh, *el, *wh, *wl, *ah, *al;
    cudaGetSymbolAddress((void**)&h,    g_h);
    cudaGetSymbolAddress((void**)&xz,   g_xz);
    cudaGetSymbolAddress((void**)&xi,   g_xi);
    cudaGetSymbolAddress((void**)&bcd,  g_bcd);
    cudaGetSymbolAddress((void**)&bcdp, g_bcdp);
    cudaGetSymbolAddress((void**)&delta,g_delta);
    cudaGetSymbolAddress((void**)&eh,   g_eh);
    cudaGetSymbolAddress((void**)&el,   g_el);
    cudaGetSymbolAddress((void**)&wh,   g_wh);
    cudaGetSymbolAddress((void**)&wl,   g_wl);
    cudaGetSymbolAddress((void**)&ah,   g_ah);
    cudaGetSymbolAddress((void**)&al,   g_al);

    const int SMB = GS_STAGES * GS_BYTES;   // 147456
    cudaFuncSetAttribute(gemm_mma, cudaFuncAttributeMaxDynamicSharedMemorySize, SMB);

    #define CVT8(src, dh, dl, rows, K, Kpad, lda, off) \
        cvt8_k<<<((rows)*((Kpad)/8) + 255) / 256, 256>>>(src, dh, dl, rows, K, Kpad, lda, off)

    // launch #4 = first gemm_mma (in_proj) so ncu captures the GEMM
    CVT8(in_w, wh, wl, 2 * DI, D, D, D, 0);
    embed_k<<<TOK, 256>>>(x, emb, h);

    for (int l = 0; l < NL; l++) {
        const float* in_wl = in_w   + (size_t)l * 2 * DI * D;
        const float* cwl   = conv_w + (size_t)l * DI * KCONV;
        const float* cbl   = conv_b + (size_t)l * DI;
        const float* lAl   = lA     + (size_t)l * DI * NSTATE;
        const float* bcwl  = bcw    + (size_t)l * BCDW * DI;
        const float* dwl   = dup_w  + (size_t)l * DI * DR;
        const float* dbl   = dup_b  + (size_t)l * DI;
        const float* Dpl   = D_param + (size_t)l * DI;
        const float* owl   = out_w  + (size_t)l * D * DI;

        rmsnorm_bf_k<<<TOK, 256>>>(h, rms_w + (size_t)l * D, ah, al);
        if (l > 0) CVT8(in_wl, wh, wl, 2 * DI, D, D, D, 0);
        gemm_mma<<<dim3(TOK / 128, (2 * DI) / 128), 256, SMB>>>(ah, al, wh, xz,
                2 * DI, D, D, 2 * DI, 0, 0);
        conv_silu_k<<<(TOK * DI / 2 + 255) / 256, 256>>>(xz, cwl, cbl, xi, ah, al);
        CVT8(bcwl, wh, wl, BCDW, DI, DI, DI, 0);
        // bcd GEMM: deterministic split-K over 8 chunks of 192
        gemm_mma<<<dim3(TOK / 128, 1, BCD_SPLIT), 256, SMB>>>(ah, al, wh, bcdp,
                BCDW, DI, BCD_KCHUNK, BCDW, 0, TOK * BCDW);
        redk<<<(TOK * BCDW + 255) / 256, 256>>>(bcdp, bcd);
        CVT8(bcd, ah, al, TOK, DR, 64, BCDW, 2 * NSTATE);
        CVT8(dwl, wh, wl, DI, DR, 64, DR, 0);
        gemm_mma<<<dim3(TOK / 128, DI / 128), 256, SMB>>>(ah, al, wh, delta,
                DI, 64, 64, DI, 0, 0);
        scan_k<<<BB * (DI / 8), 128>>>(lAl, Dpl, bcd, delta, dbl, xi, xz, ah, al);
        CVT8(owl, wh, wl, D, DI, DI, DI, 0);
        gemm_mma<<<dim3(TOK / 128, D / 128), 256, SMB>>>(ah, al, wh, h,
                D, DI, DI, D, 1, 0);        // accum=1: fused residual
    }

    CVT8(emb, eh, el, VOC, D, D, D, 0);
    rmsnorm_bf_k<<<TOK, 256>>>(h, norm_f_w, ah, al);
    gemm_mma<<<dim3(TOK / 128, VOC / 128), 256, SMB>>>(ah, al, eh, out,
            VOC, D, D, VOC, 0, 0);
}